// round 15
// baseline (speedup 1.0000x reference)
#include <cuda_runtime.h>
#include <math.h>

#define BATCH 4
#define SEQ 4096
#define HID 512
#define HD 64
#define BS (BATCH*SEQ)          // 16384

// ---------------- scratch (device globals; no allocations allowed) ----------
__device__ float g_qT[HD*BS];   // q transposed: [d][global_row]
__device__ float g_kT[HD*BS];   // k transposed: [d][global_row]
__device__ float g_v[BS*HD];    // v row-major:  [global_row][d]
__device__ float g_score[(size_t)BATCH*SEQ*SEQ];   // 256 MiB raw scores
__device__ float g_colsum[BS];
__device__ float g_cfac[BS];
__device__ float g_rinv[BS];

// ---------------- f32x2 packed-FMA helpers ----------------------------------
__device__ __forceinline__ void ffma2(unsigned long long& d,
                                      unsigned long long a,
                                      unsigned long long b) {
    asm("fma.rn.f32x2 %0, %1, %2, %0;" : "+l"(d) : "l"(a), "l"(b));
}
__device__ __forceinline__ unsigned long long dup2(float x) {
    unsigned long long r;
    asm("mov.b64 %0, {%1, %1};" : "=l"(r) : "f"(x));
    return r;
}
__device__ __forceinline__ float2 unpk2(unsigned long long v) {
    float2 f;
    asm("mov.b64 {%0, %1}, %2;" : "=f"(f.x), "=f"(f.y) : "l"(v));
    return f;
}

// ---------------- kernel 0: zero column sums (graph replays!) ---------------
__global__ void zero_kernel() {
    int i = blockIdx.x * blockDim.x + threadIdx.x;
    if (i < BS) g_colsum[i] = 0.0f;
}

// ---------------- kernel 1: projection + bias + L2 normalize ----------------
// grid (BS/64, 3), block 256. q,k written TRANSPOSED ([d][row]); v row-major.
__global__ __launch_bounds__(256) void proj_kernel(
    const float* __restrict__ x,
    const float* __restrict__ Wq, const float* __restrict__ bq,
    const float* __restrict__ Wk, const float* __restrict__ bk,
    const float* __restrict__ Wv, const float* __restrict__ bv)
{
    const float* W; const float* bias;
    int p = blockIdx.y;
    if (p == 0)      { W = Wq; bias = bq; }
    else if (p == 1) { W = Wk; bias = bk; }
    else             { W = Wv; bias = bv; }

    __shared__ float xs[64][33];
    __shared__ float ws[32][64];
    __shared__ float ts[64][65];
    int tid = threadIdx.x;
    int tx = tid & 15, ty = tid >> 4;
    int row0 = blockIdx.x * 64;

    float acc[4][4];
#pragma unroll
    for (int i = 0; i < 4; i++)
#pragma unroll
        for (int j = 0; j < 4; j++) acc[i][j] = 0.0f;

    for (int kk = 0; kk < HID; kk += 32) {
#pragma unroll
        for (int l = 0; l < 8; l++) {
            int idx = tid + l * 256;
            int r = idx >> 5, c = idx & 31;
            xs[r][c] = x[(size_t)(row0 + r) * HID + kk + c];
            int k2 = idx >> 6, d = idx & 63;
            ws[k2][d] = W[(kk + k2) * HD + d];
        }
        __syncthreads();
#pragma unroll 8
        for (int k = 0; k < 32; k++) {
            float a[4], b[4];
#pragma unroll
            for (int i = 0; i < 4; i++) a[i] = xs[ty * 4 + i][k];
#pragma unroll
            for (int j = 0; j < 4; j++) b[j] = ws[k][tx * 4 + j];
#pragma unroll
            for (int i = 0; i < 4; i++)
#pragma unroll
                for (int j = 0; j < 4; j++) acc[i][j] += a[i] * b[j];
        }
        __syncthreads();
    }
#pragma unroll
    for (int j = 0; j < 4; j++) {
        float bb = bias[tx * 4 + j];
#pragma unroll
        for (int i = 0; i < 4; i++) acc[i][j] += bb;
    }
    __shared__ float rs[64];
    if (tid < 64) rs[tid] = 0.0f;
    __syncthreads();
#pragma unroll
    for (int i = 0; i < 4; i++) {
        float s = acc[i][0] * acc[i][0] + acc[i][1] * acc[i][1]
                + acc[i][2] * acc[i][2] + acc[i][3] * acc[i][3];
        atomicAdd(&rs[ty * 4 + i], s);
    }
    __syncthreads();
    if (p == 2) {
#pragma unroll
        for (int i = 0; i < 4; i++) {
            float inv = 1.0f / fmaxf(sqrtf(rs[ty * 4 + i]), 1e-12f);
            int row = row0 + ty * 4 + i;
#pragma unroll
            for (int j = 0; j < 4; j++)
                g_v[(size_t)row * HD + tx * 4 + j] = acc[i][j] * inv;
        }
    } else {
        // stage in smem, write transposed & coalesced
#pragma unroll
        for (int i = 0; i < 4; i++) {
            float inv = 1.0f / fmaxf(sqrtf(rs[ty * 4 + i]), 1e-12f);
#pragma unroll
            for (int j = 0; j < 4; j++)
                ts[ty * 4 + i][tx * 4 + j] = acc[i][j] * inv;
        }
        __syncthreads();
        float* outT = (p == 0) ? g_qT : g_kT;
#pragma unroll
        for (int l = 0; l < 16; l++) {
            int idx = tid + l * 256;           // 0..4095
            int r = idx & 63, d = idx >> 6;
            outT[(size_t)d * BS + row0 + r] = ts[r][d];
        }
    }
}

// ---------------- kernel 2: score = (1+arccos(q.k))^-3.5, + column sums -----
// grid (SEQ/128, SEQ/128, BATCH), block 256, 8x8 micro-tile, FFMA2 inner loop.
__global__ __launch_bounds__(256, 2) void score_kernel() {
    extern __shared__ float sm[];
    float (*qs)[128] = (float (*)[128])sm;               // [64][128]
    float (*ks)[128] = (float (*)[128])(sm + 64 * 128);  // [64][128]

    int b = blockIdx.z;
    int row0 = blockIdx.y * 128;
    int col0 = blockIdx.x * 128;
    int tid = threadIdx.x;
    int tx = tid & 15, ty = tid >> 4;

    const float* qb = g_qT + (size_t)b * SEQ + row0;   // [d*BS + r]
    const float* kb = g_kT + (size_t)b * SEQ + col0;

#pragma unroll
    for (int l = 0; l < 8; l++) {
        int f = tid + l * 256;            // 0..2047 float4 slots
        int r4 = (f & 31) * 4, d = f >> 5;
        *(float4*)&qs[d][r4] = *(const float4*)&qb[(size_t)d * BS + r4];
        *(float4*)&ks[d][r4] = *(const float4*)&kb[(size_t)d * BS + r4];
    }
    __syncthreads();

    unsigned long long acc[8][4];
#pragma unroll
    for (int i = 0; i < 8; i++)
#pragma unroll
        for (int j = 0; j < 4; j++) acc[i][j] = 0ull;

    int ra = ty * 8, ca = tx * 8;
#pragma unroll 4
    for (int d = 0; d < 64; d++) {
        float4 a0 = *(const float4*)&qs[d][ra];
        float4 a1 = *(const float4*)&qs[d][ra + 4];
        ulonglong2 b0 = *(const ulonglong2*)&ks[d][ca];
        ulonglong2 b1 = *(const ulonglong2*)&ks[d][ca + 4];
        unsigned long long A[8];
        A[0] = dup2(a0.x); A[1] = dup2(a0.y); A[2] = dup2(a0.z); A[3] = dup2(a0.w);
        A[4] = dup2(a1.x); A[5] = dup2(a1.y); A[6] = dup2(a1.z); A[7] = dup2(a1.w);
#pragma unroll
        for (int i = 0; i < 8; i++) {
            ffma2(acc[i][0], A[i], b0.x);
            ffma2(acc[i][1], A[i], b0.y);
            ffma2(acc[i][2], A[i], b1.x);
            ffma2(acc[i][3], A[i], b1.y);
        }
    }

    // epilogue: transcendental + store + column sums
    float csum[8];
#pragma unroll
    for (int j = 0; j < 8; j++) csum[j] = 0.0f;

    float* srow = g_score + (size_t)b * SEQ * SEQ;
#pragma unroll
    for (int i = 0; i < 8; i++) {
        float v[8];
        float2 p;
        p = unpk2(acc[i][0]); v[0] = p.x; v[1] = p.y;
        p = unpk2(acc[i][1]); v[2] = p.x; v[3] = p.y;
        p = unpk2(acc[i][2]); v[4] = p.x; v[5] = p.y;
        p = unpk2(acc[i][3]); v[6] = p.x; v[7] = p.y;
        float sc[8];
#pragma unroll
        for (int j = 0; j < 8; j++) {
            float c = fminf(fmaxf(v[j], -1.0f + 1e-7f), 1.0f - 1e-7f);
            float gd = acosf(c);
            sc[j] = __expf(-3.5f * __logf(1.0f + gd));
            csum[j] += sc[j];
        }
        size_t off = (size_t)(row0 + ra + i) * SEQ + col0 + ca;
        *(float4*)&srow[off]     = make_float4(sc[0], sc[1], sc[2], sc[3]);
        *(float4*)&srow[off + 4] = make_float4(sc[4], sc[5], sc[6], sc[7]);
    }

    // column-sum reduction: smem atomics then one global atomic per column
    __syncthreads();                  // tiles no longer needed, reuse sm
    float* cred = sm;                 // 128 entries
    if (tid < 128) cred[tid] = 0.0f;
    __syncthreads();
#pragma unroll
    for (int j = 0; j < 8; j++) atomicAdd(&cred[ca + j], csum[j]);
    __syncthreads();
    if (tid < 128) atomicAdd(&g_colsum[b * SEQ + col0 + tid], cred[tid]);
}

// ---------------- kernel 3: cfac = colsum^-0.5 ------------------------------
__global__ void cfac_kernel() {
    int i = blockIdx.x * blockDim.x + threadIdx.x;
    if (i < BS) g_cfac[i] = 1.0f / sqrtf(g_colsum[i]);
}

// ---------------- kernel 4: row sums of score*cfac -> rinv ------------------
__global__ __launch_bounds__(256) void rowsum_kernel() {
    int row = blockIdx.x;                 // [0, BS)
    int b = row >> 12;
    const float* sr = g_score + (size_t)row * SEQ;
    const float* cf = g_cfac + b * SEQ;
    int tid = threadIdx.x;
    float sum = 0.0f;
    for (int t = tid * 4; t < SEQ; t += 256 * 4) {
        float4 sv = *(const float4*)(sr + t);
        float4 cv = *(const float4*)(cf + t);
        sum += sv.x * cv.x + sv.y * cv.y + sv.z * cv.z + sv.w * cv.w;
    }
#pragma unroll
    for (int off = 16; off; off >>= 1)
        sum += __shfl_xor_sync(0xffffffffu, sum, off);
    __shared__ float wsum[8];
    int lane = tid & 31, w = tid >> 5;
    if (lane == 0) wsum[w] = sum;
    __syncthreads();
    if (tid == 0) {
        float tot = 0.0f;
#pragma unroll
        for (int i = 0; i < 8; i++) tot += wsum[i];
        g_rinv[row] = 1.0f / fmaxf(tot, 1e-12f);
    }
}

// ---------------- kernel 5: probs write + PV GEMM (cfac folded into V) ------
// grid (SEQ/64, BATCH), block 256, 4x4 micro-tile, k-vectorized x4, FFMA2.
__global__ __launch_bounds__(256, 2) void out_kernel(float* __restrict__ outp,
                                                     float* __restrict__ probsp)
{
    __shared__ float ss[64][68];   // raw score chunk [r][t]
    __shared__ float vv[64][64];   // v*cfac chunk [t][d]
    __shared__ float rin[64];

    int b = blockIdx.y;
    int row0 = blockIdx.x * 64;
    int tid = threadIdx.x;
    int tx = tid & 15, ty = tid >> 4;

    if (tid < 64) rin[tid] = g_rinv[b * SEQ + row0 + tid];

    const float* sbase = g_score + (size_t)(b * SEQ + row0) * SEQ;
    const float* vb = g_v + (size_t)b * SEQ * HD;
    const float* cf = g_cfac + b * SEQ;
    float* pb = probsp ? probsp + (size_t)(b * SEQ + row0) * SEQ : (float*)0;

    unsigned long long acc[4][2];
#pragma unroll
    for (int i = 0; i < 4; i++) { acc[i][0] = 0ull; acc[i][1] = 0ull; }

    for (int tt = 0; tt < SEQ; tt += 64) {
        __syncthreads();   // previous compute done (and rin visible, iter 0)
        // stage raw scores; write probs inline (pure streaming pass)
#pragma unroll
        for (int l = 0; l < 4; l++) {
            int f = tid + l * 256;          // 0..1023 float4 slots (64x64)
            int r = f >> 4, c4 = (f & 15) * 4;
            float4 sv = *(const float4*)&sbase[(size_t)r * SEQ + tt + c4];
            *(float4*)&ss[r][c4] = sv;
            if (pb) {
                float4 cv = *(const float4*)&cf[tt + c4];
                float rv = rin[r];
                float4 pvv = make_float4(sv.x * cv.x * rv, sv.y * cv.y * rv,
                                         sv.z * cv.z * rv, sv.w * cv.w * rv);
                *(float4*)&pb[(size_t)r * SEQ + tt + c4] = pvv;
            }
        }
        // stage V scaled by cfac[t]
#pragma unroll
        for (int l = 0; l < 4; l++) {
            int f = tid + l * 256;
            int r = f >> 4, c4 = (f & 15) * 4;
            float4 vvv = *(const float4*)&vb[(size_t)(tt + r) * HD + c4];
            float cfr = cf[tt + r];
            vvv.x *= cfr; vvv.y *= cfr; vvv.z *= cfr; vvv.w *= cfr;
            *(float4*)&vv[r][c4] = vvv;
        }
        __syncthreads();

#pragma unroll 4
        for (int k4 = 0; k4 < 64; k4 += 4) {
            float4 a[4];
#pragma unroll
            for (int i = 0; i < 4; i++)
                a[i] = *(const float4*)&ss[ty * 4 + i][k4];
            ulonglong2 bb[4];
#pragma unroll
            for (int kk = 0; kk < 4; kk++)
                bb[kk] = *(const ulonglong2*)&vv[k4 + kk][tx * 4];
#pragma unroll
            for (int kk = 0; kk < 4; kk++) {
                float av[4] = {0, 0, 0, 0};
                // select kk-th component of each a[i]
#pragma unroll
                for (int i = 0; i < 4; i++) {
                    float s = (kk == 0) ? a[i].x : (kk == 1) ? a[i].y
                              : (kk == 2) ? a[i].z : a[i].w;
                    av[i] = s;
                }
#pragma unroll
                for (int i = 0; i < 4; i++) {
                    unsigned long long A = dup2(av[i]);
                    ffma2(acc[i][0], A, bb[kk].x);
                    ffma2(acc[i][1], A, bb[kk].y);
                }
            }
        }
    }

    if (outp) {
#pragma unroll
        for (int i = 0; i < 4; i++) {
            float ri = rin[ty * 4 + i];
            int row = b * SEQ + row0 + ty * 4 + i;
            float2 p0 = unpk2(acc[i][0]);
            float2 p1 = unpk2(acc[i][1]);
            float4 o = make_float4(p0.x * ri, p0.y * ri, p1.x * ri, p1.y * ri);
            *(float4*)&outp[(size_t)row * HD + tx * 4] = o;
        }
    }
}

// ---------------- launch ----------------------------------------------------
extern "C" void kernel_launch(void* const* d_in, const int* in_sizes, int n_in,
                              void* d_out, int out_size)
{
    const float* x  = (const float*)d_in[0];
    const float* Wq = (const float*)d_in[1];
    const float* bq = (const float*)d_in[2];
    const float* Wk = (const float*)d_in[3];
    const float* bk = (const float*)d_in[4];
    const float* Wv = (const float*)d_in[5];
    const float* bv = (const float*)d_in[6];

    const long long OUTE = (long long)BATCH * SEQ * HD;    // 1,048,576
    const long long PRBE = (long long)BATCH * SEQ * SEQ;   // 67,108,864
    float* outp = (float*)0;
    float* probsp = (float*)0;
    long long osz = (long long)out_size;
    if (osz >= OUTE + PRBE) {           // concatenated (output, probs)
        outp = (float*)d_out;
        probsp = (float*)d_out + OUTE;
    } else if (osz >= PRBE) {           // probs only
        probsp = (float*)d_out;
    } else {                            // output only
        outp = (float*)d_out;
    }

    cudaFuncSetAttribute(score_kernel,
                         cudaFuncAttributeMaxDynamicSharedMemorySize, 65536);

    zero_kernel<<<(BS + 255) / 256, 256>>>();
    dim3 pg(BS / 64, 3);
    proj_kernel<<<pg, 256>>>(x, Wq, bq, Wk, bk, Wv, bv);
    dim3 sg(SEQ / 128, SEQ / 128, BATCH);
    score_kernel<<<sg, 256, 65536>>>();
    cfac_kernel<<<(BS + 255) / 256, 256>>>();
    rowsum_kernel<<<BS, 256>>>();
    dim3 og(SEQ / 64, BATCH);
    out_kernel<<<og, 256>>>(outp, probsp);
}

// round 16
// speedup vs baseline: 1.1136x; 1.1136x over previous
#include <cuda_runtime.h>
#include <cuda_fp16.h>
#include <math.h>

#define BATCH 4
#define SEQ 4096
#define HID 512
#define HD 64
#define BS (BATCH*SEQ)          // 16384

// ---------------- scratch (device globals; no allocations allowed) ----------
__device__ float g_qT[HD*BS];   // q transposed: [d][global_row]
__device__ float g_kT[HD*BS];   // k transposed: [d][global_row]
__device__ float g_v[BS*HD];    // v row-major:  [global_row][d]
__device__ __half g_score[(size_t)BATCH*SEQ*SEQ];  // 128 MiB raw scores (fp16)
__device__ float g_colsum[BS];
__device__ float g_cfac[BS];
__device__ float g_rinv[BS];

// ---------------- f32x2 packed-FMA helpers ----------------------------------
__device__ __forceinline__ void ffma2(unsigned long long& d,
                                      unsigned long long a,
                                      unsigned long long b) {
    asm("fma.rn.f32x2 %0, %1, %2, %0;" : "+l"(d) : "l"(a), "l"(b));
}
__device__ __forceinline__ unsigned long long dup2(float x) {
    unsigned long long r;
    asm("mov.b64 %0, {%1, %1};" : "=l"(r) : "f"(x));
    return r;
}
__device__ __forceinline__ float2 unpk2(unsigned long long v) {
    float2 f;
    asm("mov.b64 {%0, %1}, %2;" : "=f"(f.x), "=f"(f.y) : "l"(v));
    return f;
}

// ---------------- score transform: (1 + acos(c))^-3.5 -----------------------
// Branchless acos: asin 13th-order odd poly (|err|<6e-7 on |s|<=0.5),
// sqrt-fold for |c|>0.5. Power via rsqrt^7 (1 MUFU + 3 MUL).
__device__ __forceinline__ float score_fn(float v) {
    float c = fminf(fmaxf(v, -1.0f + 1e-7f), 1.0f - 1e-7f);
    float t = fabsf(c);
    bool big = t > 0.5f;
    float zs = sqrtf(fmaf(t, -0.5f, 0.5f));   // sqrt((1-t)/2)
    float s = big ? zs : t;
    float p = s * s;
    float poly = 0.017352765f;
    poly = fmaf(poly, p, 0.022372159f);
    poly = fmaf(poly, p, 0.030381944f);
    poly = fmaf(poly, p, 0.044642857f);
    poly = fmaf(poly, p, 0.075f);
    poly = fmaf(poly, p, 0.16666667f);
    float r = fmaf(s * p, poly, s);           // asin(s)
    float ap = big ? (2.0f * r) : (1.5707963268f - r);
    float gd = (c < 0.0f) ? (3.1415926536f - ap) : ap;   // acos(c)
    float rs = rsqrtf(1.0f + gd);
    float r2 = rs * rs;
    float r4 = r2 * r2;
    return r4 * r2 * rs;                      // (1+gd)^-3.5
}

// ---------------- kernel 0: zero column sums (graph replays!) ---------------
__global__ void zero_kernel() {
    int i = blockIdx.x * blockDim.x + threadIdx.x;
    if (i < BS) g_colsum[i] = 0.0f;
}

// ---------------- kernel 1: projection + bias + L2 normalize ----------------
__global__ __launch_bounds__(256) void proj_kernel(
    const float* __restrict__ x,
    const float* __restrict__ Wq, const float* __restrict__ bq,
    const float* __restrict__ Wk, const float* __restrict__ bk,
    const float* __restrict__ Wv, const float* __restrict__ bv)
{
    const float* W; const float* bias;
    int p = blockIdx.y;
    if (p == 0)      { W = Wq; bias = bq; }
    else if (p == 1) { W = Wk; bias = bk; }
    else             { W = Wv; bias = bv; }

    __shared__ float xs[64][33];
    __shared__ float ws[32][64];
    __shared__ float ts[64][65];
    int tid = threadIdx.x;
    int tx = tid & 15, ty = tid >> 4;
    int row0 = blockIdx.x * 64;

    float acc[4][4];
#pragma unroll
    for (int i = 0; i < 4; i++)
#pragma unroll
        for (int j = 0; j < 4; j++) acc[i][j] = 0.0f;

    for (int kk = 0; kk < HID; kk += 32) {
#pragma unroll
        for (int l = 0; l < 8; l++) {
            int idx = tid + l * 256;
            int r = idx >> 5, c = idx & 31;
            xs[r][c] = x[(size_t)(row0 + r) * HID + kk + c];
            int k2 = idx >> 6, d = idx & 63;
            ws[k2][d] = W[(kk + k2) * HD + d];
        }
        __syncthreads();
#pragma unroll 8
        for (int k = 0; k < 32; k++) {
            float a[4], b[4];
#pragma unroll
            for (int i = 0; i < 4; i++) a[i] = xs[ty * 4 + i][k];
#pragma unroll
            for (int j = 0; j < 4; j++) b[j] = ws[k][tx * 4 + j];
#pragma unroll
            for (int i = 0; i < 4; i++)
#pragma unroll
                for (int j = 0; j < 4; j++) acc[i][j] += a[i] * b[j];
        }
        __syncthreads();
    }
#pragma unroll
    for (int j = 0; j < 4; j++) {
        float bb = bias[tx * 4 + j];
#pragma unroll
        for (int i = 0; i < 4; i++) acc[i][j] += bb;
    }
    __shared__ float rs[64];
    if (tid < 64) rs[tid] = 0.0f;
    __syncthreads();
#pragma unroll
    for (int i = 0; i < 4; i++) {
        float s = acc[i][0] * acc[i][0] + acc[i][1] * acc[i][1]
                + acc[i][2] * acc[i][2] + acc[i][3] * acc[i][3];
        atomicAdd(&rs[ty * 4 + i], s);
    }
    __syncthreads();
    if (p == 2) {
#pragma unroll
        for (int i = 0; i < 4; i++) {
            float inv = 1.0f / fmaxf(sqrtf(rs[ty * 4 + i]), 1e-12f);
            int row = row0 + ty * 4 + i;
#pragma unroll
            for (int j = 0; j < 4; j++)
                g_v[(size_t)row * HD + tx * 4 + j] = acc[i][j] * inv;
        }
    } else {
#pragma unroll
        for (int i = 0; i < 4; i++) {
            float inv = 1.0f / fmaxf(sqrtf(rs[ty * 4 + i]), 1e-12f);
#pragma unroll
            for (int j = 0; j < 4; j++)
                ts[ty * 4 + i][tx * 4 + j] = acc[i][j] * inv;
        }
        __syncthreads();
        float* outT = (p == 0) ? g_qT : g_kT;
#pragma unroll
        for (int l = 0; l < 16; l++) {
            int idx = tid + l * 256;           // 0..4095
            int r = idx & 63, d = idx >> 6;
            outT[(size_t)d * BS + row0 + r] = ts[r][d];
        }
    }
}

// ---------------- kernel 2: scores (fp16 store) + column sums ---------------
// grid (SEQ/128, SEQ/128, BATCH), block 256, 8x8 micro-tile, FFMA2 inner loop.
__global__ __launch_bounds__(256, 2) void score_kernel() {
    extern __shared__ float sm[];
    float (*qs)[128] = (float (*)[128])sm;               // [64][128]
    float (*ks)[128] = (float (*)[128])(sm + 64 * 128);  // [64][128]

    int b = blockIdx.z;
    int row0 = blockIdx.y * 128;
    int col0 = blockIdx.x * 128;
    int tid = threadIdx.x;
    int tx = tid & 15, ty = tid >> 4;

    const float* qb = g_qT + (size_t)b * SEQ + row0;   // [d*BS + r]
    const float* kb = g_kT + (size_t)b * SEQ + col0;

#pragma unroll
    for (int l = 0; l < 8; l++) {
        int f = tid + l * 256;            // 0..2047 float4 slots
        int r4 = (f & 31) * 4, d = f >> 5;
        *(float4*)&qs[d][r4] = *(const float4*)&qb[(size_t)d * BS + r4];
        *(float4*)&ks[d][r4] = *(const float4*)&kb[(size_t)d * BS + r4];
    }
    __syncthreads();

    unsigned long long acc[8][4];
#pragma unroll
    for (int i = 0; i < 8; i++)
#pragma unroll
        for (int j = 0; j < 4; j++) acc[i][j] = 0ull;

    int ra = ty * 8, ca = tx * 8;
#pragma unroll 4
    for (int d = 0; d < 64; d++) {
        float4 a0 = *(const float4*)&qs[d][ra];
        float4 a1 = *(const float4*)&qs[d][ra + 4];
        ulonglong2 b0 = *(const ulonglong2*)&ks[d][ca];
        ulonglong2 b1 = *(const ulonglong2*)&ks[d][ca + 4];
        unsigned long long A[8];
        A[0] = dup2(a0.x); A[1] = dup2(a0.y); A[2] = dup2(a0.z); A[3] = dup2(a0.w);
        A[4] = dup2(a1.x); A[5] = dup2(a1.y); A[6] = dup2(a1.z); A[7] = dup2(a1.w);
#pragma unroll
        for (int i = 0; i < 8; i++) {
            ffma2(acc[i][0], A[i], b0.x);
            ffma2(acc[i][1], A[i], b0.y);
            ffma2(acc[i][2], A[i], b1.x);
            ffma2(acc[i][3], A[i], b1.y);
        }
    }

    // epilogue: transform + fp16 store + column sums
    float csum[8];
#pragma unroll
    for (int j = 0; j < 8; j++) csum[j] = 0.0f;

    __half* srow = g_score + (size_t)b * SEQ * SEQ;
#pragma unroll
    for (int i = 0; i < 8; i++) {
        float v[8];
        float2 p;
        p = unpk2(acc[i][0]); v[0] = p.x; v[1] = p.y;
        p = unpk2(acc[i][1]); v[2] = p.x; v[3] = p.y;
        p = unpk2(acc[i][2]); v[4] = p.x; v[5] = p.y;
        p = unpk2(acc[i][3]); v[6] = p.x; v[7] = p.y;
        float sc[8];
#pragma unroll
        for (int j = 0; j < 8; j++) {
            sc[j] = score_fn(v[j]);
            csum[j] += sc[j];
        }
        __half2 hh[4];
#pragma unroll
        for (int j = 0; j < 4; j++)
            hh[j] = __floats2half2_rn(sc[2 * j], sc[2 * j + 1]);
        size_t off = (size_t)(row0 + ra + i) * SEQ + col0 + ca;
        *(uint4*)&srow[off] = *(uint4*)hh;
    }

    // column-sum reduction: smem atomics then one global atomic per column
    __syncthreads();                  // tiles no longer needed, reuse sm
    float* cred = sm;                 // 128 entries
    if (tid < 128) cred[tid] = 0.0f;
    __syncthreads();
#pragma unroll
    for (int j = 0; j < 8; j++) atomicAdd(&cred[ca + j], csum[j]);
    __syncthreads();
    if (tid < 128) atomicAdd(&g_colsum[b * SEQ + col0 + tid], cred[tid]);
}

// ---------------- kernel 3: cfac = colsum^-0.5 ------------------------------
__global__ void cfac_kernel() {
    int i = blockIdx.x * blockDim.x + threadIdx.x;
    if (i < BS) g_cfac[i] = 1.0f / sqrtf(g_colsum[i]);
}

// ---------------- kernel 4: row sums of score*cfac -> rinv ------------------
__global__ __launch_bounds__(256) void rowsum_kernel() {
    int row = blockIdx.x;                 // [0, BS)
    int b = row >> 12;
    const __half* sr = g_score + (size_t)row * SEQ;
    const float* cf = g_cfac + b * SEQ;
    int tid = threadIdx.x;
    float sum = 0.0f;
    for (int t = tid * 8; t < SEQ; t += 256 * 8) {
        uint4 pk = *(const uint4*)(sr + t);
        __half2* hp = (__half2*)&pk;
        float4 c0 = *(const float4*)(cf + t);
        float4 c1 = *(const float4*)(cf + t + 4);
        float2 f0 = __half22float2(hp[0]);
        float2 f1 = __half22float2(hp[1]);
        float2 f2 = __half22float2(hp[2]);
        float2 f3 = __half22float2(hp[3]);
        sum += f0.x * c0.x + f0.y * c0.y + f1.x * c0.z + f1.y * c0.w
             + f2.x * c1.x + f2.y * c1.y + f3.x * c1.z + f3.y * c1.w;
    }
#pragma unroll
    for (int off = 16; off; off >>= 1)
        sum += __shfl_xor_sync(0xffffffffu, sum, off);
    __shared__ float wsum[8];
    int lane = tid & 31, w = tid >> 5;
    if (lane == 0) wsum[w] = sum;
    __syncthreads();
    if (tid == 0) {
        float tot = 0.0f;
#pragma unroll
        for (int i = 0; i < 8; i++) tot += wsum[i];
        g_rinv[row] = 1.0f / fmaxf(tot, 1e-12f);
    }
}

// ---------------- kernel 5: probs write + PV GEMM (cfac folded into V) ------
__global__ __launch_bounds__(256, 2) void out_kernel(float* __restrict__ outp,
                                                     float* __restrict__ probsp)
{
    __shared__ float ss[64][72];   // raw score chunk [r][t] (float, converted)
    __shared__ float vv[64][64];   // v*cfac chunk [t][d]
    __shared__ float rin[64];

    int b = blockIdx.y;
    int row0 = blockIdx.x * 64;
    int tid = threadIdx.x;
    int tx = tid & 15, ty = tid >> 4;

    if (tid < 64) rin[tid] = g_rinv[b * SEQ + row0 + tid];

    const __half* sbase = g_score + (size_t)(b * SEQ + row0) * SEQ;
    const float* vb = g_v + (size_t)b * SEQ * HD;
    const float* cf = g_cfac + b * SEQ;
    float* pb = probsp ? probsp + (size_t)(b * SEQ + row0) * SEQ : (float*)0;

    unsigned long long acc[4][2];
#pragma unroll
    for (int i = 0; i < 4; i++) { acc[i][0] = 0ull; acc[i][1] = 0ull; }

    for (int tt = 0; tt < SEQ; tt += 64) {
        __syncthreads();   // previous compute done (and rin visible, iter 0)
        // stage raw scores (half -> float); write probs inline
#pragma unroll
        for (int l = 0; l < 2; l++) {
            int f = tid + l * 256;          // 0..511 half8 slots (64x64)
            int r = f >> 3, c8 = (f & 7) * 8;
            uint4 pk = *(const uint4*)&sbase[(size_t)r * SEQ + tt + c8];
            __half2* hp = (__half2*)&pk;
            float2 f0 = __half22float2(hp[0]);
            float2 f1 = __half22float2(hp[1]);
            float2 f2 = __half22float2(hp[2]);
            float2 f3 = __half22float2(hp[3]);
            *(float4*)&ss[r][c8]     = make_float4(f0.x, f0.y, f1.x, f1.y);
            *(float4*)&ss[r][c8 + 4] = make_float4(f2.x, f2.y, f3.x, f3.y);
            if (pb) {
                float4 c0 = *(const float4*)&cf[tt + c8];
                float4 c1 = *(const float4*)&cf[tt + c8 + 4];
                float rv = rin[r];
                float4 p0 = make_float4(f0.x * c0.x * rv, f0.y * c0.y * rv,
                                        f1.x * c0.z * rv, f1.y * c0.w * rv);
                float4 p1 = make_float4(f2.x * c1.x * rv, f2.y * c1.y * rv,
                                        f3.x * c1.z * rv, f3.y * c1.w * rv);
                *(float4*)&pb[(size_t)r * SEQ + tt + c8]     = p0;
                *(float4*)&pb[(size_t)r * SEQ + tt + c8 + 4] = p1;
            }
        }
        // stage V scaled by cfac[t]
#pragma unroll
        for (int l = 0; l < 4; l++) {
            int f = tid + l * 256;
            int r = f >> 4, c4 = (f & 15) * 4;
            float4 vvv = *(const float4*)&vb[(size_t)(tt + r) * HD + c4];
            float cfr = cf[tt + r];
            vvv.x *= cfr; vvv.y *= cfr; vvv.z *= cfr; vvv.w *= cfr;
            *(float4*)&vv[r][c4] = vvv;
        }
        __syncthreads();

#pragma unroll 4
        for (int k4 = 0; k4 < 64; k4 += 4) {
            float4 a[4];
#pragma unroll
            for (int i = 0; i < 4; i++)
                a[i] = *(const float4*)&ss[ty * 4 + i][k4];
            ulonglong2 bb[4];
#pragma unroll
            for (int kk = 0; kk < 4; kk++)
                bb[kk] = *(const ulonglong2*)&vv[k4 + kk][tx * 4];
#pragma unroll
            for (int kk = 0; kk < 4; kk++) {
                float av[4];
#pragma unroll
                for (int i = 0; i < 4; i++) {
                    float s = (kk == 0) ? a[i].x : (kk == 1) ? a[i].y
                              : (kk == 2) ? a[i].z : a[i].w;
                    av[i] = s;
                }
#pragma unroll
                for (int i = 0; i < 4; i++) {
                    unsigned long long A = dup2(av[i]);
                    ffma2(acc[i][0], A, bb[kk].x);
                    ffma2(acc[i][1], A, bb[kk].y);
                }
            }
        }
    }

    if (outp) {
#pragma unroll
        for (int i = 0; i < 4; i++) {
            float ri = rin[ty * 4 + i];
            int row = b * SEQ + row0 + ty * 4 + i;
            float2 p0 = unpk2(acc[i][0]);
            float2 p1 = unpk2(acc[i][1]);
            float4 o = make_float4(p0.x * ri, p0.y * ri, p1.x * ri, p1.y * ri);
            *(float4*)&outp[(size_t)row * HD + tx * 4] = o;
        }
    }
}

// ---------------- launch ----------------------------------------------------
extern "C" void kernel_launch(void* const* d_in, const int* in_sizes, int n_in,
                              void* d_out, int out_size)
{
    const float* x  = (const float*)d_in[0];
    const float* Wq = (const float*)d_in[1];
    const float* bq = (const float*)d_in[2];
    const float* Wk = (const float*)d_in[3];
    const float* bk = (const float*)d_in[4];
    const float* Wv = (const float*)d_in[5];
    const float* bv = (const float*)d_in[6];

    const long long OUTE = (long long)BATCH * SEQ * HD;    // 1,048,576
    const long long PRBE = (long long)BATCH * SEQ * SEQ;   // 67,108,864
    float* outp = (float*)0;
    float* probsp = (float*)0;
    long long osz = (long long)out_size;
    if (osz >= OUTE + PRBE) {           // concatenated (output, probs)
        outp = (float*)d_out;
        probsp = (float*)d_out + OUTE;
    } else if (osz >= PRBE) {           // probs only
        probsp = (float*)d_out;
    } else {                            // output only
        outp = (float*)d_out;
    }

    cudaFuncSetAttribute(score_kernel,
                         cudaFuncAttributeMaxDynamicSharedMemorySize, 65536);

    zero_kernel<<<(BS + 255) / 256, 256>>>();
    dim3 pg(BS / 64, 3);
    proj_kernel<<<pg, 256>>>(x, Wq, bq, Wk, bk, Wv, bv);
    dim3 sg(SEQ / 128, SEQ / 128, BATCH);
    score_kernel<<<sg, 256, 65536>>>();
    cfac_kernel<<<(BS + 255) / 256, 256>>>();
    rowsum_kernel<<<BS, 256>>>();
    dim3 og(SEQ / 64, BATCH);
    out_kernel<<<og, 256>>>(outp, probsp);
}

// round 17
// speedup vs baseline: 1.4863x; 1.3347x over previous
#include <cuda_runtime.h>
#include <cuda_fp16.h>
#include <math.h>

#define BATCH 4
#define SEQ 4096
#define HID 512
#define HD 64
#define BS (BATCH*SEQ)          // 16384

// ---------------- scratch (device globals; no allocations allowed) ----------
__device__ __half g_qh[BS*HD];  // q fp16 row-major [row][d]
__device__ __half g_kh[BS*HD];  // k fp16 row-major [row][d]
__device__ float  g_v[BS*HD];   // v fp32 row-major [row][d]
__device__ __half g_score[(size_t)BATCH*SEQ*SEQ];  // 128 MiB raw scores (fp16)
__device__ float  g_colsum[BS];
__device__ float  g_cfac[BS];
__device__ float  g_rinv[BS];

// ---------------- mma.m16n8k16 fp16->fp32 helper ----------------------------
__device__ __forceinline__ void mma16816(float* c, const unsigned* a,
                                         const unsigned* b) {
    asm volatile(
        "mma.sync.aligned.m16n8k16.row.col.f32.f16.f16.f32 "
        "{%0,%1,%2,%3}, {%4,%5,%6,%7}, {%8,%9}, {%0,%1,%2,%3};"
        : "+f"(c[0]), "+f"(c[1]), "+f"(c[2]), "+f"(c[3])
        : "r"(a[0]), "r"(a[1]), "r"(a[2]), "r"(a[3]), "r"(b[0]), "r"(b[1]));
}

// ---------------- score transform: (1 + acos(c))^-3.5 -----------------------
__device__ __forceinline__ float score_fn(float v) {
    float c = fminf(fmaxf(v, -1.0f + 1e-7f), 1.0f - 1e-7f);
    float t = fabsf(c);
    bool big = t > 0.5f;
    float zs = sqrtf(fmaf(t, -0.5f, 0.5f));   // sqrt((1-t)/2)
    float s = big ? zs : t;
    float p = s * s;
    float poly = 0.017352765f;
    poly = fmaf(poly, p, 0.022372159f);
    poly = fmaf(poly, p, 0.030381944f);
    poly = fmaf(poly, p, 0.044642857f);
    poly = fmaf(poly, p, 0.075f);
    poly = fmaf(poly, p, 0.16666667f);
    float r = fmaf(s * p, poly, s);           // asin(s)
    float ap = big ? (2.0f * r) : (1.5707963268f - r);
    float gd = (c < 0.0f) ? (3.1415926536f - ap) : ap;   // acos(c)
    float rs = rsqrtf(1.0f + gd);
    float r2 = rs * rs;
    float r4 = r2 * r2;
    return r4 * r2 * rs;                      // (1+gd)^-3.5
}

// ---------------- kernel 0: zero column sums (graph replays!) ---------------
__global__ void zero_kernel() {
    int i = blockIdx.x * blockDim.x + threadIdx.x;
    if (i < BS) g_colsum[i] = 0.0f;
}

// ---------------- kernel 1: projection + bias + L2 normalize ----------------
// grid (BS/64, 3), block 256. q,k written fp16 row-major; v fp32 row-major.
__global__ __launch_bounds__(256) void proj_kernel(
    const float* __restrict__ x,
    const float* __restrict__ Wq, const float* __restrict__ bq,
    const float* __restrict__ Wk, const float* __restrict__ bk,
    const float* __restrict__ Wv, const float* __restrict__ bv)
{
    const float* W; const float* bias;
    int p = blockIdx.y;
    if (p == 0)      { W = Wq; bias = bq; }
    else if (p == 1) { W = Wk; bias = bk; }
    else             { W = Wv; bias = bv; }

    __shared__ float xs[64][33];
    __shared__ float ws[32][64];
    int tid = threadIdx.x;
    int tx = tid & 15, ty = tid >> 4;
    int row0 = blockIdx.x * 64;

    float acc[4][4];
#pragma unroll
    for (int i = 0; i < 4; i++)
#pragma unroll
        for (int j = 0; j < 4; j++) acc[i][j] = 0.0f;

    for (int kk = 0; kk < HID; kk += 32) {
#pragma unroll
        for (int l = 0; l < 8; l++) {
            int idx = tid + l * 256;
            int r = idx >> 5, c = idx & 31;
            xs[r][c] = x[(size_t)(row0 + r) * HID + kk + c];
            int k2 = idx >> 6, d = idx & 63;
            ws[k2][d] = W[(kk + k2) * HD + d];
        }
        __syncthreads();
#pragma unroll 8
        for (int k = 0; k < 32; k++) {
            float a[4], b[4];
#pragma unroll
            for (int i = 0; i < 4; i++) a[i] = xs[ty * 4 + i][k];
#pragma unroll
            for (int j = 0; j < 4; j++) b[j] = ws[k][tx * 4 + j];
#pragma unroll
            for (int i = 0; i < 4; i++)
#pragma unroll
                for (int j = 0; j < 4; j++) acc[i][j] += a[i] * b[j];
        }
        __syncthreads();
    }
#pragma unroll
    for (int j = 0; j < 4; j++) {
        float bb = bias[tx * 4 + j];
#pragma unroll
        for (int i = 0; i < 4; i++) acc[i][j] += bb;
    }
    __shared__ float rs[64];
    if (tid < 64) rs[tid] = 0.0f;
    __syncthreads();
#pragma unroll
    for (int i = 0; i < 4; i++) {
        float s = acc[i][0] * acc[i][0] + acc[i][1] * acc[i][1]
                + acc[i][2] * acc[i][2] + acc[i][3] * acc[i][3];
        atomicAdd(&rs[ty * 4 + i], s);
    }
    __syncthreads();
    if (p == 2) {
#pragma unroll
        for (int i = 0; i < 4; i++) {
            float inv = 1.0f / fmaxf(sqrtf(rs[ty * 4 + i]), 1e-12f);
            int row = row0 + ty * 4 + i;
#pragma unroll
            for (int j = 0; j < 4; j++)
                g_v[(size_t)row * HD + tx * 4 + j] = acc[i][j] * inv;
        }
    } else {
        __half* outH = (p == 0) ? g_qh : g_kh;
#pragma unroll
        for (int i = 0; i < 4; i++) {
            float inv = 1.0f / fmaxf(sqrtf(rs[ty * 4 + i]), 1e-12f);
            int row = row0 + ty * 4 + i;
            __half2 h0 = __floats2half2_rn(acc[i][0] * inv, acc[i][1] * inv);
            __half2 h1 = __floats2half2_rn(acc[i][2] * inv, acc[i][3] * inv);
            __half2* dst = (__half2*)&outH[(size_t)row * HD + tx * 4];
            dst[0] = h0; dst[1] = h1;
        }
    }
}

// ---------------- kernel 2: scores via HMMA + transform + column sums -------
// grid (SEQ/128, SEQ/128, BATCH), block 256 (8 warps: 2 m-groups x 4 n-groups)
#define SKP 72   // smem stride in halfs (144B = 9*16B; conflict-free frag loads)
__global__ __launch_bounds__(256) void score_kernel() {
    __shared__ __half qs[128 * SKP];
    __shared__ __half ks[128 * SKP];
    __shared__ float cred[128];

    int b = blockIdx.z;
    int row0 = blockIdx.y * 128;
    int col0 = blockIdx.x * 128;
    int tid = threadIdx.x, lane = tid & 31, warp = tid >> 5;
    int wm = warp & 1, wn = warp >> 1;

    const __half* qb = g_qh + (size_t)(b * SEQ + row0) * HD;
    const __half* kb = g_kh + (size_t)(b * SEQ + col0) * HD;
#pragma unroll
    for (int l = 0; l < 4; l++) {
        int idx = tid + l * 256;          // 0..1023 : 128 rows x 8 chunks
        int r = idx >> 3, c8 = (idx & 7) * 8;
        *(uint4*)&qs[r * SKP + c8] = *(const uint4*)&qb[(size_t)r * HD + c8];
        *(uint4*)&ks[r * SKP + c8] = *(const uint4*)&kb[(size_t)r * HD + c8];
    }
    __syncthreads();

    float acc[4][4][4];
#pragma unroll
    for (int mt = 0; mt < 4; mt++)
#pragma unroll
        for (int nt = 0; nt < 4; nt++)
#pragma unroll
            for (int e = 0; e < 4; e++) acc[mt][nt][e] = 0.0f;

    int arow = wm * 64 + (lane >> 2);
    int akl  = (lane & 3) * 2;
    int bcol = wn * 32 + (lane >> 2);

#pragma unroll
    for (int kk = 0; kk < 4; kk++) {
        int k0 = kk * 16;
        unsigned A[4][4], B[4][2];
#pragma unroll
        for (int mt = 0; mt < 4; mt++) {
            const __half* ab = &qs[(arow + mt * 16) * SKP + k0 + akl];
            A[mt][0] = *(const unsigned*)ab;
            A[mt][1] = *(const unsigned*)(ab + 8 * SKP);
            A[mt][2] = *(const unsigned*)(ab + 8);
            A[mt][3] = *(const unsigned*)(ab + 8 * SKP + 8);
        }
#pragma unroll
        for (int nt = 0; nt < 4; nt++) {
            const __half* bb = &ks[(bcol + nt * 8) * SKP + k0 + akl];
            B[nt][0] = *(const unsigned*)bb;
            B[nt][1] = *(const unsigned*)(bb + 8);
        }
#pragma unroll
        for (int mt = 0; mt < 4; mt++)
#pragma unroll
            for (int nt = 0; nt < 4; nt++)
                mma16816(acc[mt][nt], A[mt], B[nt]);
    }

    // epilogue: transform + fp16 store + column sums
    float csum[8];
#pragma unroll
    for (int j = 0; j < 8; j++) csum[j] = 0.0f;

    __half* srow = g_score + (size_t)b * SEQ * SEQ;
#pragma unroll
    for (int mt = 0; mt < 4; mt++) {
#pragma unroll
        for (int rr = 0; rr < 2; rr++) {
            int grow = row0 + wm * 64 + mt * 16 + (lane >> 2) + rr * 8;
#pragma unroll
            for (int nt = 0; nt < 4; nt++) {
                float s0 = score_fn(acc[mt][nt][rr * 2]);
                float s1 = score_fn(acc[mt][nt][rr * 2 + 1]);
                csum[nt * 2]     += s0;
                csum[nt * 2 + 1] += s1;
                int gcol = col0 + wn * 32 + nt * 8 + (lane & 3) * 2;
                *(__half2*)&srow[(size_t)grow * SEQ + gcol] =
                    __floats2half2_rn(s0, s1);
            }
        }
    }

    if (tid < 128) cred[tid] = 0.0f;
    __syncthreads();
#pragma unroll
    for (int nt = 0; nt < 4; nt++) {
        int cbase = wn * 32 + nt * 8 + (lane & 3) * 2;
        atomicAdd(&cred[cbase],     csum[nt * 2]);
        atomicAdd(&cred[cbase + 1], csum[nt * 2 + 1]);
    }
    __syncthreads();
    if (tid < 128) atomicAdd(&g_colsum[b * SEQ + col0 + tid], cred[tid]);
}

// ---------------- kernel 3: cfac = colsum^-0.5 ------------------------------
__global__ void cfac_kernel() {
    int i = blockIdx.x * blockDim.x + threadIdx.x;
    if (i < BS) g_cfac[i] = 1.0f / sqrtf(g_colsum[i]);
}

// ---------------- kernel 4: row sums of score*cfac -> rinv ------------------
__global__ __launch_bounds__(256) void rowsum_kernel() {
    int row = blockIdx.x;                 // [0, BS)
    int b = row >> 12;
    const __half* sr = g_score + (size_t)row * SEQ;
    const float* cf = g_cfac + b * SEQ;
    int tid = threadIdx.x;
    float sum = 0.0f;
    for (int t = tid * 8; t < SEQ; t += 256 * 8) {
        uint4 pk = *(const uint4*)(sr + t);
        __half2* hp = (__half2*)&pk;
        float4 c0 = *(const float4*)(cf + t);
        float4 c1 = *(const float4*)(cf + t + 4);
        float2 f0 = __half22float2(hp[0]);
        float2 f1 = __half22float2(hp[1]);
        float2 f2 = __half22float2(hp[2]);
        float2 f3 = __half22float2(hp[3]);
        sum += f0.x * c0.x + f0.y * c0.y + f1.x * c0.z + f1.y * c0.w
             + f2.x * c1.x + f2.y * c1.y + f3.x * c1.z + f3.y * c1.w;
    }
#pragma unroll
    for (int off = 16; off; off >>= 1)
        sum += __shfl_xor_sync(0xffffffffu, sum, off);
    __shared__ float wsum[8];
    int lane = tid & 31, w = tid >> 5;
    if (lane == 0) wsum[w] = sum;
    __syncthreads();
    if (tid == 0) {
        float tot = 0.0f;
#pragma unroll
        for (int i = 0; i < 8; i++) tot += wsum[i];
        g_rinv[row] = 1.0f / fmaxf(tot, 1e-12f);
    }
}

// ---------------- kernel 5: probs write + PV GEMM via HMMA ------------------
// grid (SEQ/64, BATCH), block 256 (8 warps: 4 m-groups x 2 n-groups)
#define VTP 66   // vt smem stride in halfs ([d][t], conflict-free)
__global__ __launch_bounds__(256) void out_kernel(float* __restrict__ outp,
                                                  float* __restrict__ probsp)
{
    __shared__ __half ss[64 * SKP];   // score chunk [m][t]
    __shared__ __half vt[64 * VTP];   // (v*cfac)^T chunk [d][t]
    __shared__ float rin[64];

    int b = blockIdx.y;
    int row0 = blockIdx.x * 64;
    int tid = threadIdx.x, lane = tid & 31, warp = tid >> 5;
    int wm = warp & 3, wn = warp >> 2;

    if (tid < 64) rin[tid] = g_rinv[b * SEQ + row0 + tid];

    const __half* sbase = g_score + (size_t)(b * SEQ + row0) * SEQ;
    const float* vb = g_v + (size_t)b * SEQ * HD;
    const float* cf = g_cfac + b * SEQ;
    float* pb = probsp ? probsp + (size_t)(b * SEQ + row0) * SEQ : (float*)0;

    float acc[4][4];
#pragma unroll
    for (int nt = 0; nt < 4; nt++)
#pragma unroll
        for (int e = 0; e < 4; e++) acc[nt][e] = 0.0f;

    int arow = wm * 16 + (lane >> 2);
    int akl  = (lane & 3) * 2;
    int bcol = wn * 32 + (lane >> 2);

    // V staging mapping: d spans lanes (coalesced), t uniform per warp-iter
    int vd = tid & 63;
    int vt0 = (tid >> 6) * 16;

    for (int tt = 0; tt < SEQ; tt += 64) {
        __syncthreads();   // previous chunk's compute done (rin visible, iter0)
        // stage raw scores (fp16 passthrough); write probs inline
#pragma unroll
        for (int l = 0; l < 2; l++) {
            int f = tid + l * 256;          // 0..511 : 64 rows x 8 chunks
            int r = f >> 3, c8 = (f & 7) * 8;
            uint4 pk = *(const uint4*)&sbase[(size_t)r * SEQ + tt + c8];
            *(uint4*)&ss[r * SKP + c8] = pk;
            if (pb) {
                __half2* hp = (__half2*)&pk;
                float2 f0 = __half22float2(hp[0]);
                float2 f1 = __half22float2(hp[1]);
                float2 f2 = __half22float2(hp[2]);
                float2 f3 = __half22float2(hp[3]);
                float4 c0 = *(const float4*)&cf[tt + c8];
                float4 c1 = *(const float4*)&cf[tt + c8 + 4];
                float rv = rin[r];
                float4 p0 = make_float4(f0.x * c0.x * rv, f0.y * c0.y * rv,
                                        f1.x * c0.z * rv, f1.y * c0.w * rv);
                float4 p1 = make_float4(f2.x * c1.x * rv, f2.y * c1.y * rv,
                                        f3.x * c1.z * rv, f3.y * c1.w * rv);
                *(float4*)&pb[(size_t)r * SEQ + tt + c8]     = p0;
                *(float4*)&pb[(size_t)r * SEQ + tt + c8 + 4] = p1;
            }
        }
        // stage V*cfac transposed into vt[d][t]
#pragma unroll
        for (int i = 0; i < 16; i++) {
            int t = vt0 + i;
            float cfr = cf[tt + t];
            float v = vb[(size_t)(tt + t) * HD + vd];
            vt[vd * VTP + t] = __float2half(v * cfr);
        }
        __syncthreads();

#pragma unroll
        for (int kk = 0; kk < 4; kk++) {
            int k0 = kk * 16;
            unsigned A[4], B[4][2];
            const __half* ab = &ss[arow * SKP + k0 + akl];
            A[0] = *(const unsigned*)ab;
            A[1] = *(const unsigned*)(ab + 8 * SKP);
            A[2] = *(const unsigned*)(ab + 8);
            A[3] = *(const unsigned*)(ab + 8 * SKP + 8);
#pragma unroll
            for (int nt = 0; nt < 4; nt++) {
                const __half* bb = &vt[(bcol + nt * 8) * VTP + k0 + akl];
                B[nt][0] = *(const unsigned*)bb;
                B[nt][1] = *(const unsigned*)(bb + 8);
            }
#pragma unroll
            for (int nt = 0; nt < 4; nt++)
                mma16816(acc[nt], A, B[nt]);
        }
    }

    if (outp) {
#pragma unroll
        for (int rr = 0; rr < 2; rr++) {
            int lrow = wm * 16 + (lane >> 2) + rr * 8;
            float ri = rin[lrow];
            int grow = b * SEQ + row0 + lrow;
#pragma unroll
            for (int nt = 0; nt < 4; nt++) {
                int gcol = wn * 32 + nt * 8 + (lane & 3) * 2;
                float2 o = make_float2(acc[nt][rr * 2] * ri,
                                       acc[nt][rr * 2 + 1] * ri);
                *(float2*)&outp[(size_t)grow * HD + gcol] = o;
            }
        }
    }
}

// ---------------- launch ----------------------------------------------------
extern "C" void kernel_launch(void* const* d_in, const int* in_sizes, int n_in,
                              void* d_out, int out_size)
{
    const float* x  = (const float*)d_in[0];
    const float* Wq = (const float*)d_in[1];
    const float* bq = (const float*)d_in[2];
    const float* Wk = (const float*)d_in[3];
    const float* bk = (const float*)d_in[4];
    const float* Wv = (const float*)d_in[5];
    const float* bv = (const float*)d_in[6];

    const long long OUTE = (long long)BATCH * SEQ * HD;    // 1,048,576
    const long long PRBE = (long long)BATCH * SEQ * SEQ;   // 67,108,864
    float* outp = (float*)0;
    float* probsp = (float*)0;
    long long osz = (long long)out_size;
    if (osz >= OUTE + PRBE) {           // concatenated (output, probs)
        outp = (float*)d_out;
        probsp = (float*)d_out + OUTE;
    } else if (osz >= PRBE) {           // probs only
        probsp = (float*)d_out;
    } else {                            // output only
        outp = (float*)d_out;
    }

    zero_kernel<<<(BS + 255) / 256, 256>>>();
    dim3 pg(BS / 64, 3);
    proj_kernel<<<pg, 256>>>(x, Wq, bq, Wk, bk, Wv, bv);
    dim3 sg(SEQ / 128, SEQ / 128, BATCH);
    score_kernel<<<sg, 256>>>();
    cfac_kernel<<<(BS + 255) / 256, 256>>>();
    rowsum_kernel<<<BS, 256>>>();
    dim3 og(SEQ / 64, BATCH);
    out_kernel<<<og, 256>>>(outp, probsp);
}